// round 9
// baseline (speedup 1.0000x reference)
#include <cuda_runtime.h>
#include <cstdint>
#include <math_constants.h>

#define TPB 256
#define NCTAS 296

__device__ unsigned int g_counter;

__global__ void init_counter_kernel() { g_counter = 0u; }

__device__ __forceinline__ unsigned long long pk2(float lo, float hi) {
    unsigned long long r;
    asm("mov.b64 %0, {%1, %2};" : "=l"(r) : "f"(lo), "f"(hi));
    return r;
}
__device__ __forceinline__ void upk2(unsigned long long v, float& lo, float& hi) {
    asm("mov.b64 {%0, %1}, %2;" : "=f"(lo), "=f"(hi) : "l"(v));
}
// Packed fp32x2 FMA (Blackwell): per-lane IEEE rn FMA, identical rounding to scalar fmaf.
__device__ __forceinline__ unsigned long long ffma2(unsigned long long a,
                                                    unsigned long long b,
                                                    unsigned long long c) {
    unsigned long long d;
    asm("fma.rn.f32x2 %0, %1, %2, %3;" : "=l"(d) : "l"(a), "l"(b), "l"(c));
    return d;
}

__global__ __launch_bounds__(TPB, 2) void e8p_kernel(
    const float* __restrict__ X,
    const float* __restrict__ grid,       // [n_grid, 8]
    const float* __restrict__ gnorm,      // [n_grid]
    const int*   __restrict__ allcombo,   // [128, n_grid]
    const int*   __restrict__ idx_map,    // [256]
    float* __restrict__ out,
    int N, int n_grid, int ngp, int idx_mode)
{
    // Candidate record: 5 ulonglong2 = 80 B:
    //   [0..3] = (g0,g0),(g1,g1) | (g2,g2),(g3,g3) | (g4,g4),(g5,g5) | (g6,g6),(g7,g7)
    //   [4].x  = (-norm,-norm). Records q in [n_grid, ngp+2) are sentinels
    //   (g=0, nn=-inf) so prefetch overrun is harmless and they never win.
    extern __shared__ ulonglong2 srec[];
    int* simap = (int*)(srec + (size_t)(ngp + 2) * 5);   // [256]

    for (int q = threadIdx.x; q < ngp + 2; q += TPB) {
        ulonglong2* rrec = srec + (size_t)q * 5;
        if (q < n_grid) {
            const float* g = grid + (size_t)q * 8;
            #pragma unroll
            for (int p = 0; p < 4; p++)
                rrec[p] = make_ulonglong2(pk2(g[2 * p], g[2 * p]),
                                          pk2(g[2 * p + 1], g[2 * p + 1]));
            float nn = -gnorm[q];
            rrec[4] = make_ulonglong2(pk2(nn, nn), 0ull);
        } else {
            #pragma unroll
            for (int p = 0; p < 4; p++) rrec[p] = make_ulonglong2(0ull, 0ull);
            rrec[4] = make_ulonglong2(pk2(-CUDART_INF_F, -CUDART_INF_F), 0ull);
        }
    }
    if (threadIdx.x < 256) simap[threadIdx.x] = idx_map[threadIdx.x];
    __syncthreads();

    const int nchunks = N >> 6;          // 64 rows per chunk (2 per lane)
    const int lane = threadIdx.x & 31;
    const unsigned long long ZERO = pk2(0.0f, 0.0f);
    const unsigned long long TWO  = pk2(2.0f, 2.0f);
    const float* sgf = (const float*)srec;   // g_j of candidate q at sgf[q*20 + j*2]

    while (true) {
        unsigned c;
        if (lane == 0) c = atomicAdd(&g_counter, 1u);
        c = __shfl_sync(0xFFFFFFFFu, c, 0);
        if (c >= (unsigned)nchunks) break;
        const int base = (int)(c << 6);
        int rows[2] = {base + lane, base + 32 + lane};

        unsigned negp[2], negm[2], pp[2], pm[2];
        unsigned long long ya[2][8];

        #pragma unroll
        for (int r = 0; r < 2; r++) {
            const float4* X4 = (const float4*)(X + (size_t)rows[r] * 8);
            float4 xa = X4[0], xb = X4[1];
            float xr[8] = {xa.x, xa.y, xa.z, xa.w, xb.x, xb.y, xb.z, xb.w};

            unsigned np = 0u, nm = 0u;
            float ap[8], am[8];
            #pragma unroll
            for (int j = 0; j < 8; j++) {
                float yp = __fadd_rn(xr[j], 0.25f);
                float ym = __fsub_rn(xr[j], 0.25f);
                if (yp < 0.0f) np |= 1u << j;
                if (ym < 0.0f) nm |= 1u << j;
                ap[j] = fabsf(yp);
                am[j] = fabsf(ym);
            }
            pp[r] = __popc(np) & 1u;
            pm[r] = __popc(nm) & 1u;
            negp[r] = np; negm[r] = nm;
            if (pp[r]) ap[0] = -ap[0];
            if (pm[r]) am[0] = -am[0];
            #pragma unroll
            for (int j = 0; j < 8; j++) ya[r][j] = pk2(ap[j], am[j]);
        }

        float bsp[2] = {-CUDART_INF_F, -CUDART_INF_F};
        float bsm[2] = {-CUDART_INF_F, -CUDART_INF_F};
        int qp[2] = {0, 0}, qm[2] = {0, 0};

        // Double-buffered prefetch: while scoring candidate q (buffer A/B),
        // the 5 LDS for q+1 land in the other buffer. Unroll x2, no rotation.
        ulonglong2 a01 = srec[0], a23 = srec[1], a45 = srec[2], a67 = srec[3];
        unsigned long long nnA = srec[4].x;

        for (int q = 0; q < ngp; q += 2) {
            // Prefetch q+1 into B.
            const ulonglong2* gB = srec + (size_t)(q + 1) * 5;
            ulonglong2 b01 = gB[0], b23 = gB[1], b45 = gB[2], b67 = gB[3];
            unsigned long long nnB = gB[4].x;

            #pragma unroll
            for (int r = 0; r < 2; r++) {
                unsigned long long acc = ffma2(a01.x, ya[r][0], ZERO);
                acc = ffma2(a01.y, ya[r][1], acc);
                acc = ffma2(a23.x, ya[r][2], acc);
                acc = ffma2(a23.y, ya[r][3], acc);
                acc = ffma2(a45.x, ya[r][4], acc);
                acc = ffma2(a45.y, ya[r][5], acc);
                acc = ffma2(a67.x, ya[r][6], acc);
                acc = ffma2(a67.y, ya[r][7], acc);
                unsigned long long s2 = ffma2(TWO, acc, nnA);
                float sp, sm;
                upk2(s2, sp, sm);
                if (sp > bsp[r]) { bsp[r] = sp; qp[r] = q; }
                if (sm > bsm[r]) { bsm[r] = sm; qm[r] = q; }
            }

            // Prefetch q+2 into A.
            const ulonglong2* gA = srec + (size_t)(q + 2) * 5;
            a01 = gA[0]; a23 = gA[1]; a45 = gA[2]; a67 = gA[3];
            nnA = gA[4].x;

            #pragma unroll
            for (int r = 0; r < 2; r++) {
                unsigned long long acc = ffma2(b01.x, ya[r][0], ZERO);
                acc = ffma2(b01.y, ya[r][1], acc);
                acc = ffma2(b23.x, ya[r][2], acc);
                acc = ffma2(b23.y, ya[r][3], acc);
                acc = ffma2(b45.x, ya[r][4], acc);
                acc = ffma2(b45.y, ya[r][5], acc);
                acc = ffma2(b67.x, ya[r][6], acc);
                acc = ffma2(b67.y, ya[r][7], acc);
                unsigned long long s2 = ffma2(TWO, acc, nnB);
                float sp, sm;
                upk2(s2, sp, sm);
                if (sp > bsp[r]) { bsp[r] = sp; qp[r] = q + 1; }
                if (sm > bsm[r]) { bsm[r] = sm; qm[r] = q + 1; }
            }
        }

        // Epilogue per row: direct residuals with reference rounding.
        #pragma unroll
        for (int r = 0; r < 2; r++) {
            const unsigned mnegp = negp[r] ^ pp[r];   // parity flips bit 0
            const unsigned mnegm = negm[r] ^ pm[r];
            float e2p = 0.0f, e2m = 0.0f;
            #pragma unroll
            for (int j = 0; j < 8; j++) {
                float apj, amj;
                upk2(ya[r][j], apj, amj);
                float yp = ((negp[r] >> j) & 1u) ? -fabsf(apj) : fabsf(apj);
                float ym = ((negm[r] >> j) & 1u) ? -fabsf(amj) : fabsf(amj);
                float gp_ = sgf[qp[r] * 20 + j * 2];
                float gm_ = sgf[qm[r] * 20 + j * 2];
                float vpj = ((mnegp >> j) & 1u) ? -gp_ : gp_;
                float vmj = ((mnegm >> j) & 1u) ? -gm_ : gm_;
                float dp = __fsub_rn(yp, vpj);
                float dm = __fsub_rn(ym, vmj);
                e2p = __fadd_rn(e2p, __fmul_rn(dp, dp));
                e2m = __fadd_rn(e2m, __fmul_rn(dm, dm));
            }
            const bool which = __fsqrt_rn(e2p) < __fsqrt_rn(e2m);

            const int q = which ? qp[r] : qm[r];
            const unsigned mneg = which ? mnegp : mnegm;
            const float delta = which ? -0.25f : 0.25f;

            const int mint = (int)(__brev(mneg & 0xFFu) >> 24);  // bit j -> 2^(7-j)
            const int r128 = simap[mint];
            const int ridx = __ldg(&allcombo[(size_t)r128 * n_grid + q]);
            const int fidx = which ? ridx : (ridx - 32768);

            float v[8];
            #pragma unroll
            for (int j = 0; j < 8; j++) {
                float g = sgf[q * 20 + j * 2];
                float sg = ((mneg >> j) & 1u) ? -g : g;    // grid*mask (exact)
                v[j] = __fadd_rn(sg, delta);               // fl(vals -/+ 0.25)
            }
            float4* O = (float4*)(out + (size_t)rows[r] * 8);
            O[0] = make_float4(v[0], v[1], v[2], v[3]);
            O[1] = make_float4(v[4], v[5], v[6], v[7]);

            if (idx_mode == 1) {
                out[(size_t)N * 8 + rows[r]] = (float)fidx;
            } else if (idx_mode == 2) {
                ((short*)(out + (size_t)N * 8))[rows[r]] = (short)fidx;
            }
        }
    }
}

extern "C" void kernel_launch(void* const* d_in, const int* in_sizes, int n_in,
                              void* d_out, int out_size) {
    const float* X        = (const float*)d_in[0];
    const float* grid     = (const float*)d_in[1];
    const float* gnorm    = (const float*)d_in[2];
    const int*   allcombo = (const int*)d_in[3];
    const int*   idx_map  = (const int*)d_in[4];

    const int N = in_sizes[0] / 8;
    const int n_grid = in_sizes[2];
    const int ngp = (n_grid + 1) & ~1;       // even candidate count

    int idx_mode = 0;
    if (out_size >= N * 9) idx_mode = 1;                     // idx stored as floats
    else if (out_size >= N * 8 + (N + 1) / 2) idx_mode = 2;  // idx packed as int16

    size_t smem_bytes = (size_t)(ngp + 2) * 80 + 1024 + 64;
    cudaFuncSetAttribute(e8p_kernel, cudaFuncAttributeMaxDynamicSharedMemorySize,
                         (int)smem_bytes);

    init_counter_kernel<<<1, 1>>>();
    e8p_kernel<<<NCTAS, TPB, smem_bytes>>>(X, grid, gnorm, allcombo, idx_map,
                                           (float*)d_out, N, n_grid, ngp, idx_mode);
}